// round 8
// baseline (speedup 1.0000x reference)
#include <cuda_runtime.h>
#include <math.h>

#define GRID  592            /* 148 SMs x 4 CTAs: one exact wave at occ 4 */
#define TPB   256
#define STRIDE (GRID * TPB)  /* 151552 */

__device__ float g_part_nll[GRID];
__device__ float g_part_w1[GRID];
__device__ float g_part_w2[GRID];
__device__ unsigned int g_count = 0;   // atomicInc wraps to 0 each launch

// log2(picked): picked = label ? p : 1-p, clamped at 1e-8.
// x = p + g, g = l ? +0.0f : -1.0f via carry-wrapping IMAD; picked = |x|.
static __device__ __forceinline__ float pick_lg2(float p, unsigned int l) {
    float g = __uint_as_float(l * 0x40800000u + 0xBF800000u);
    float x = p + g;
    float pick = fmaxf(fabsf(x), 1e-8f);
    return __log2f(pick);
}

static __device__ __forceinline__ float e4(float4 p, uint4 l) {
    return (pick_lg2(p.x, l.x) + pick_lg2(p.y, l.y))
         + (pick_lg2(p.z, l.z) + pick_lg2(p.w, l.w));
}

static __device__ __forceinline__ float sq4(float4 v, float a) {
    a = fmaf(v.x, v.x, a); a = fmaf(v.y, v.y, a);
    a = fmaf(v.z, v.z, a); a = fmaf(v.w, v.w, a);
    return a;
}

static __device__ __forceinline__ float warp_red(float v) {
    #pragma unroll
    for (int o = 16; o; o >>= 1) v += __shfl_down_sync(0xFFFFFFFFu, v, o);
    return v;
}
static __device__ __forceinline__ double warp_red_d(double v) {
    #pragma unroll
    for (int o = 16; o; o >>= 1) v += __shfl_down_sync(0xFFFFFFFFu, v, o);
    return v;
}

extern "C" __global__ void __launch_bounds__(TPB, 4)
fused_kernel(const float4* __restrict__ p4,
             const uint4*  __restrict__ l4,
             const float4* __restrict__ w1,
             const float4* __restrict__ w2,
             float* __restrict__ out,
             int nq, int nw1, int nw2, double invN) {
    const int t0 = blockIdx.x * TPB + threadIdx.x;

    // NLL: unroll x4 across grid-stride -> 8 independent LDG.128 per round.
    float acc0 = 0.0f, acc1 = 0.0f, acc2 = 0.0f, acc3 = 0.0f;
    int i = t0;
    for (; i + 3 * STRIDE < nq; i += 4 * STRIDE) {
        float4 pa = __ldcs(p4 + i);
        float4 pb = __ldcs(p4 + i + STRIDE);
        float4 pc = __ldcs(p4 + i + 2 * STRIDE);
        float4 pd = __ldcs(p4 + i + 3 * STRIDE);
        uint4  la = __ldcs(l4 + i);
        uint4  lb = __ldcs(l4 + i + STRIDE);
        uint4  lc = __ldcs(l4 + i + 2 * STRIDE);
        uint4  ld = __ldcs(l4 + i + 3 * STRIDE);
        acc0 += e4(pa, la);
        acc1 += e4(pb, lb);
        acc2 += e4(pc, lc);
        acc3 += e4(pd, ld);
    }
    for (; i < nq; i += STRIDE) {
        float4 pa = __ldcs(p4 + i);
        uint4  la = __ldcs(l4 + i);
        acc0 += e4(pa, la);
    }
    float accL = (acc0 + acc1) + (acc2 + acc3);   // sum of log2(picked)

    // W1 sum of squares, unroll x4.
    float b0 = 0.0f, b1 = 0.0f, b2 = 0.0f, b3 = 0.0f;
    i = t0;
    for (; i + 3 * STRIDE < nw1; i += 4 * STRIDE) {
        float4 va = __ldcs(w1 + i);
        float4 vb = __ldcs(w1 + i + STRIDE);
        float4 vc = __ldcs(w1 + i + 2 * STRIDE);
        float4 vd = __ldcs(w1 + i + 3 * STRIDE);
        b0 = sq4(va, b0); b1 = sq4(vb, b1);
        b2 = sq4(vc, b2); b3 = sq4(vd, b3);
    }
    for (; i < nw1; i += STRIDE) {
        b0 = sq4(__ldcs(w1 + i), b0);
    }
    float a1 = (b0 + b1) + (b2 + b3);

    // W2 sum of squares, unroll x4.
    float c0 = 0.0f, c1 = 0.0f, c2 = 0.0f, c3 = 0.0f;
    i = t0;
    for (; i + 3 * STRIDE < nw2; i += 4 * STRIDE) {
        float4 va = __ldcs(w2 + i);
        float4 vb = __ldcs(w2 + i + STRIDE);
        float4 vc = __ldcs(w2 + i + 2 * STRIDE);
        float4 vd = __ldcs(w2 + i + 3 * STRIDE);
        c0 = sq4(va, c0); c1 = sq4(vb, c1);
        c2 = sq4(vc, c2); c3 = sq4(vd, c3);
    }
    for (; i < nw2; i += STRIDE) {
        c0 = sq4(__ldcs(w2 + i), c0);
    }
    float a2 = (c0 + c1) + (c2 + c3);

    // Block reduction.
    __shared__ float shL[8], sh1[8], sh2[8];
    __shared__ bool  is_last;
    const int lane = threadIdx.x & 31;
    const int w    = threadIdx.x >> 5;
    accL = warp_red(accL);
    a1   = warp_red(a1);
    a2   = warp_red(a2);
    if (lane == 0) { shL[w] = accL; sh1[w] = a1; sh2[w] = a2; }
    __syncthreads();
    if (threadIdx.x == 0) {
        float vL = 0.0f, v1 = 0.0f, v2 = 0.0f;
        #pragma unroll
        for (int k = 0; k < 8; k++) { vL += shL[k]; v1 += sh1[k]; v2 += sh2[k]; }
        g_part_nll[blockIdx.x] = vL;
        g_part_w1[blockIdx.x]  = v1;
        g_part_w2[blockIdx.x]  = v2;
        __threadfence();
        unsigned int old = atomicInc(&g_count, GRID - 1);
        is_last = (old == GRID - 1);
    }
    __syncthreads();

    if (!is_last) return;

    // Last block: deterministic fp64 combine; fold ln2 and 1/N here.
    double sL = 0.0, s1 = 0.0, s2 = 0.0;
    for (int k = threadIdx.x; k < GRID; k += TPB) {
        sL += (double)__ldcg(&g_part_nll[k]);
        s1 += (double)__ldcg(&g_part_w1[k]);
        s2 += (double)__ldcg(&g_part_w2[k]);
    }
    __shared__ double dL[8], d1[8], d2[8];
    sL = warp_red_d(sL); s1 = warp_red_d(s1); s2 = warp_red_d(s2);
    if (lane == 0) { dL[w] = sL; d1[w] = s1; d2[w] = s2; }
    __syncthreads();
    if (threadIdx.x == 0) {
        double vL = 0.0, v1 = 0.0, v2 = 0.0;
        #pragma unroll
        for (int k = 0; k < 8; k++) { vL += dL[k]; v1 += d1[k]; v2 += d2[k]; }
        double nll = -vL * 0.6931471805599453 * invN;   // log2 -> ln
        double reg = 0.002 * (sqrt(v1) + sqrt(v2));
        out[0] = (float)(nll + reg);
    }
}

extern "C" void kernel_launch(void* const* d_in, const int* in_sizes, int n_in,
                              void* d_out, int out_size) {
    const float4* p4 = (const float4*)d_in[0];   // output_1: N float32
    const uint4*  l4 = (const uint4*)d_in[1];    // label: N int32
    const float4* w1 = (const float4*)d_in[2];   // W1 f32
    const float4* w2 = (const float4*)d_in[3];   // W2 f32
    const int nq  = in_sizes[0] / 4;
    const int nw1 = in_sizes[2] / 4;
    const int nw2 = in_sizes[3] / 4;
    const double invN = 1.0 / (double)in_sizes[0];

    fused_kernel<<<GRID, TPB>>>(p4, l4, w1, w2, (float*)d_out,
                                nq, nw1, nw2, invN);
}

// round 9
// speedup vs baseline: 1.0009x; 1.0009x over previous
#include <cuda_runtime.h>
#include <math.h>

#define GRID  592            /* 148 SMs x 4 CTAs: one exact wave at occ 4 */
#define TPB   256
#define NB_N  472            /* NLL blocks   (~128 MB / 472 = 271 KB each) */
#define NB_W1 60             /* W1 blocks    (16 MB / 60 = 267 KB each)    */
/* remaining 60 blocks -> W2 */

__device__ float g_part_nll[GRID];
__device__ float g_part_w1[GRID];
__device__ float g_part_w2[GRID];
__device__ unsigned int g_count = 0;   // atomicInc wraps to 0 each launch

// log2(picked): picked = label ? p : 1-p, clamped at 1e-8.
// x = p + g, g = l ? +0.0f : -1.0f via carry-wrapping IMAD; picked = |x|.
static __device__ __forceinline__ float pick_lg2(float p, unsigned int l) {
    float g = __uint_as_float(l * 0x40800000u + 0xBF800000u);
    float x = p + g;
    float pick = fmaxf(fabsf(x), 1e-8f);
    return __log2f(pick);
}

static __device__ __forceinline__ float e4(float4 p, uint4 l) {
    return (pick_lg2(p.x, l.x) + pick_lg2(p.y, l.y))
         + (pick_lg2(p.z, l.z) + pick_lg2(p.w, l.w));
}

static __device__ __forceinline__ float sq4(float4 v, float a) {
    a = fmaf(v.x, v.x, a); a = fmaf(v.y, v.y, a);
    a = fmaf(v.z, v.z, a); a = fmaf(v.w, v.w, a);
    return a;
}

static __device__ __forceinline__ float warp_red(float v) {
    #pragma unroll
    for (int o = 16; o; o >>= 1) v += __shfl_down_sync(0xFFFFFFFFu, v, o);
    return v;
}
static __device__ __forceinline__ double warp_red_d(double v) {
    #pragma unroll
    for (int o = 16; o; o >>= 1) v += __shfl_down_sync(0xFFFFFFFFu, v, o);
    return v;
}

// Sum of squares over [base, end) float4 groups, thread-strided, unroll x4.
static __device__ __forceinline__ float sumsq_range(const float4* __restrict__ w,
                                                    int base, int end) {
    float b0 = 0.0f, b1 = 0.0f, b2 = 0.0f, b3 = 0.0f;
    int i = base + threadIdx.x;
    for (; i + 3 * TPB < end; i += 4 * TPB) {
        float4 va = __ldcs(w + i);
        float4 vb = __ldcs(w + i + TPB);
        float4 vc = __ldcs(w + i + 2 * TPB);
        float4 vd = __ldcs(w + i + 3 * TPB);
        b0 = sq4(va, b0); b1 = sq4(vb, b1);
        b2 = sq4(vc, b2); b3 = sq4(vd, b3);
    }
    for (; i < end; i += TPB) {
        b0 = sq4(__ldcs(w + i), b0);
    }
    return (b0 + b1) + (b2 + b3);
}

extern "C" __global__ void __launch_bounds__(TPB, 4)
fused_kernel(const float4* __restrict__ p4,
             const uint4*  __restrict__ l4,
             const float4* __restrict__ w1,
             const float4* __restrict__ w2,
             float* __restrict__ out,
             int nq, int nw1, int nw2,
             int chunk_n, int chunk_w1, int chunk_w2, double invN) {
    const int bid = blockIdx.x;

    float accL = 0.0f, a1 = 0.0f, a2 = 0.0f;

    if (bid < NB_N) {
        // NLL stream: contiguous chunk, thread-strided, unroll x4 (8 LDG.128/round).
        const int base = bid * chunk_n;
        const int end  = min(nq, base + chunk_n);
        float acc0 = 0.0f, acc1 = 0.0f, acc2 = 0.0f, acc3 = 0.0f;
        int i = base + threadIdx.x;
        for (; i + 3 * TPB < end; i += 4 * TPB) {
            float4 pa = __ldcs(p4 + i);
            float4 pb = __ldcs(p4 + i + TPB);
            float4 pc = __ldcs(p4 + i + 2 * TPB);
            float4 pd = __ldcs(p4 + i + 3 * TPB);
            uint4  la = __ldcs(l4 + i);
            uint4  lb = __ldcs(l4 + i + TPB);
            uint4  lc = __ldcs(l4 + i + 2 * TPB);
            uint4  ld = __ldcs(l4 + i + 3 * TPB);
            acc0 += e4(pa, la);
            acc1 += e4(pb, lb);
            acc2 += e4(pc, lc);
            acc3 += e4(pd, ld);
        }
        for (; i < end; i += TPB) {
            float4 pa = __ldcs(p4 + i);
            uint4  la = __ldcs(l4 + i);
            acc0 += e4(pa, la);
        }
        accL = (acc0 + acc1) + (acc2 + acc3);   // sum of log2(picked)
    } else if (bid < NB_N + NB_W1) {
        const int b = bid - NB_N;
        const int base = b * chunk_w1;
        const int end  = min(nw1, base + chunk_w1);
        a1 = sumsq_range(w1, base, end);
    } else {
        const int b = bid - NB_N - NB_W1;
        const int base = b * chunk_w2;
        const int end  = min(nw2, base + chunk_w2);
        a2 = sumsq_range(w2, base, end);
    }

    // Block reduction (uniform across roles; two of three are zero).
    __shared__ float shL[8], sh1[8], sh2[8];
    __shared__ bool  is_last;
    const int lane = threadIdx.x & 31;
    const int w    = threadIdx.x >> 5;
    accL = warp_red(accL);
    a1   = warp_red(a1);
    a2   = warp_red(a2);
    if (lane == 0) { shL[w] = accL; sh1[w] = a1; sh2[w] = a2; }
    __syncthreads();
    if (threadIdx.x == 0) {
        float vL = 0.0f, v1 = 0.0f, v2 = 0.0f;
        #pragma unroll
        for (int k = 0; k < 8; k++) { vL += shL[k]; v1 += sh1[k]; v2 += sh2[k]; }
        g_part_nll[bid] = vL;
        g_part_w1[bid]  = v1;
        g_part_w2[bid]  = v2;
        __threadfence();
        unsigned int old = atomicInc(&g_count, GRID - 1);
        is_last = (old == GRID - 1);
    }
    __syncthreads();

    if (!is_last) return;

    // Last block: deterministic fp64 combine; fold ln2 and 1/N here.
    double sL = 0.0, s1 = 0.0, s2 = 0.0;
    for (int k = threadIdx.x; k < GRID; k += TPB) {
        sL += (double)__ldcg(&g_part_nll[k]);
        s1 += (double)__ldcg(&g_part_w1[k]);
        s2 += (double)__ldcg(&g_part_w2[k]);
    }
    __shared__ double dL[8], d1[8], d2[8];
    sL = warp_red_d(sL); s1 = warp_red_d(s1); s2 = warp_red_d(s2);
    if (lane == 0) { dL[w] = sL; d1[w] = s1; d2[w] = s2; }
    __syncthreads();
    if (threadIdx.x == 0) {
        double vL = 0.0, v1 = 0.0, v2 = 0.0;
        #pragma unroll
        for (int k = 0; k < 8; k++) { vL += dL[k]; v1 += d1[k]; v2 += d2[k]; }
        double nll = -vL * 0.6931471805599453 * invN;   // log2 -> ln
        double reg = 0.002 * (sqrt(v1) + sqrt(v2));
        out[0] = (float)(nll + reg);
    }
}

extern "C" void kernel_launch(void* const* d_in, const int* in_sizes, int n_in,
                              void* d_out, int out_size) {
    const float4* p4 = (const float4*)d_in[0];   // output_1: N float32
    const uint4*  l4 = (const uint4*)d_in[1];    // label: N int32
    const float4* w1 = (const float4*)d_in[2];   // W1 f32
    const float4* w2 = (const float4*)d_in[3];   // W2 f32
    const int nq  = in_sizes[0] / 4;
    const int nw1 = in_sizes[2] / 4;
    const int nw2 = in_sizes[3] / 4;
    const int chunk_n  = (nq  + NB_N  - 1) / NB_N;
    const int chunk_w1 = (nw1 + NB_W1 - 1) / NB_W1;
    const int nb_w2    = GRID - NB_N - NB_W1;
    const int chunk_w2 = (nw2 + nb_w2 - 1) / nb_w2;
    const double invN = 1.0 / (double)in_sizes[0];

    fused_kernel<<<GRID, TPB>>>(p4, l4, w1, w2, (float*)d_out,
                                nq, nw1, nw2, chunk_n, chunk_w1, chunk_w2, invN);
}